// round 1
// baseline (speedup 1.0000x reference)
#include <cuda_runtime.h>
#include <math.h>

#define B_   256
#define H_   1024
#define DIN  128
#define DS   64
#define KTOT 1216
#define MAXT 129
#define OUTD 194
#define NENC 65
#define NDEC 64

// ---------------- persistent state (device globals; no allocation) ----------------
__device__ float g_h[2][B_ * H_];
__device__ float g_c[B_ * H_];
__device__ float g_rt[B_ * DS];
__device__ float g_V[(size_t)MAXT * B_ * DS];
__device__ float g_s[MAXT * B_];
__device__ float g_done[B_];
__device__ float g_ro_part[4 * B_ * OUTD];

__device__ __forceinline__ float sigf(float x) { return 1.0f / (1.0f + expf(-x)); }

// ---------------- zero-init (every launch: determinism) ----------------
__global__ void init_kernel() {
    int i = blockIdx.x * blockDim.x + threadIdx.x;
    int n = blockDim.x * gridDim.x;
    for (int j = i; j < B_ * H_; j += n) { g_h[0][j] = 0.f; g_h[1][j] = 0.f; g_c[j] = 0.f; }
    for (int j = i; j < B_ * DS; j += n) g_rt[j] = 0.f;
    for (int j = i; j < MAXT * B_; j += n) g_s[j] = 0.f;
    for (int j = i; j < B_; j += n) g_done[j] = 0.f;
}

// ---------------- fused gates GEMM + LSTM pointwise ----------------
// gates(B=256, 4096) = [xt | rt | h_in](256,1216) @ W^T, W row n = gi*1024 + j
// Tile: 64 batch x 32 hidden units (=128 gate cols). grid(4,32), 256 threads.
// Each thread: 4 batches x 2 j x 4 gates = 32 accumulators.
__global__ __launch_bounds__(256) void lstm_step_kernel(
    const float* __restrict__ x, int t, int parity,
    const float* __restrict__ w_ih, const float* __restrict__ w_hh,
    const float* __restrict__ b_ih, const float* __restrict__ b_hh,
    int kStart)
{
    __shared__ float As[16][64];
    __shared__ float Bs[16][128];

    const float* h_in  = g_h[parity];
    float*       h_out = g_h[parity ^ 1];
    const float* xt = x + (size_t)t * B_ * DIN;

    int tid = threadIdx.x;
    int tx = tid & 15, ty = tid >> 4;
    int m0 = blockIdx.x * 64;
    int j0 = blockIdx.y * 32;

    float acc[4][2][4];
#pragma unroll
    for (int r = 0; r < 4; r++)
#pragma unroll
        for (int q = 0; q < 2; q++)
#pragma unroll
            for (int gi = 0; gi < 4; gi++) acc[r][q][gi] = 0.f;

    // loader indices
    int lm  = tid >> 2;           // 0..63 (batch within tile)
    int lk4 = (tid & 3) << 2;     // 0,4,8,12
    int ln  = tid >> 1;           // 0..127 (gate-col within tile)
    int lgi = ln >> 5, ljl = ln & 31;
    int lk8 = (tid & 1) << 3;     // 0,8
    const float* wrow_ih = w_ih + (size_t)(lgi * H_ + j0 + ljl) * 192;
    const float* wrow_hh = w_hh + (size_t)(lgi * H_ + j0 + ljl) * H_;

    for (int k0 = kStart; k0 < KTOT; k0 += 16) {
        // A tile (the 16-wide k slab never straddles the 128/192 boundaries)
        float4 va;
        if (k0 < 128)      va = *(const float4*)(xt   + (m0 + lm) * DIN + k0 + lk4);
        else if (k0 < 192) va = *(const float4*)(g_rt + (m0 + lm) * DS  + (k0 - 128) + lk4);
        else               va = *(const float4*)(h_in + (m0 + lm) * H_  + (k0 - 192) + lk4);
        As[lk4 + 0][lm] = va.x; As[lk4 + 1][lm] = va.y;
        As[lk4 + 2][lm] = va.z; As[lk4 + 3][lm] = va.w;

        // B tile
        const float* p = (k0 < 192) ? (wrow_ih + k0 + lk8) : (wrow_hh + (k0 - 192) + lk8);
        float4 vb0 = *(const float4*)p;
        float4 vb1 = *(const float4*)(p + 4);
        Bs[lk8 + 0][ln] = vb0.x; Bs[lk8 + 1][ln] = vb0.y;
        Bs[lk8 + 2][ln] = vb0.z; Bs[lk8 + 3][ln] = vb0.w;
        Bs[lk8 + 4][ln] = vb1.x; Bs[lk8 + 5][ln] = vb1.y;
        Bs[lk8 + 6][ln] = vb1.z; Bs[lk8 + 7][ln] = vb1.w;
        __syncthreads();

#pragma unroll
        for (int kk = 0; kk < 16; kk++) {
            float rA[4], rB[2][4];
#pragma unroll
            for (int r = 0; r < 4; r++) rA[r] = As[kk][ty + 16 * r];
#pragma unroll
            for (int q = 0; q < 2; q++)
#pragma unroll
                for (int gi = 0; gi < 4; gi++) rB[q][gi] = Bs[kk][gi * 32 + tx + 16 * q];
#pragma unroll
            for (int r = 0; r < 4; r++)
#pragma unroll
                for (int q = 0; q < 2; q++)
#pragma unroll
                    for (int gi = 0; gi < 4; gi++) acc[r][q][gi] += rA[r] * rB[q][gi];
        }
        __syncthreads();
    }

    // epilogue: LSTM pointwise
#pragma unroll
    for (int r = 0; r < 4; r++) {
        int m = m0 + ty + 16 * r;
#pragma unroll
        for (int q = 0; q < 2; q++) {
            int j = j0 + tx + 16 * q;
            float gi_v = acc[r][q][0] + b_ih[j]            + b_hh[j];
            float gf_v = acc[r][q][1] + b_ih[H_ + j]       + b_hh[H_ + j];
            float gg_v = acc[r][q][2] + b_ih[2 * H_ + j]   + b_hh[2 * H_ + j];
            float go_v = acc[r][q][3] + b_ih[3 * H_ + j]   + b_hh[3 * H_ + j];
            float cv = g_c[m * H_ + j];
            float cn = sigf(gf_v) * cv + sigf(gi_v) * tanhf(gg_v);
            float hn = sigf(go_v) * tanhf(cn);
            g_c[m * H_ + j]  = cn;
            h_out[m * H_ + j] = hn;
        }
    }
}

// ---------------- readout GEMM: out = h_new @ w_ro^T (split-K x4, partials) ----------
// grid(4, colTiles, 4), 256 threads. Tile 64 batch x 16 cols. K chunk = 256.
__global__ __launch_bounds__(256) void ro_kernel(
    int parityNew, const float* __restrict__ w_ro, int colStart)
{
    __shared__ float As[16][64];
    __shared__ float Bs[16][17];

    const float* h = g_h[parityNew];
    int tid = threadIdx.x;
    int tx = tid & 15, ty = tid >> 4;
    int m0 = blockIdx.x * 64;
    int col0 = colStart + blockIdx.y * 16;
    int ks = blockIdx.z;

    float acc[4] = {0.f, 0.f, 0.f, 0.f};
    int lm = tid >> 2, lk4 = (tid & 3) << 2;
    int myCol = col0 + ty;
    bool colOk = (myCol < OUTD);

    int kend = ks * 256 + 256;
    for (int k0 = ks * 256; k0 < kend; k0 += 16) {
        float4 va = *(const float4*)(h + (m0 + lm) * H_ + k0 + lk4);
        As[lk4 + 0][lm] = va.x; As[lk4 + 1][lm] = va.y;
        As[lk4 + 2][lm] = va.z; As[lk4 + 3][lm] = va.w;
        Bs[tx][ty] = colOk ? w_ro[(size_t)myCol * H_ + k0 + tx] : 0.f;
        __syncthreads();
#pragma unroll
        for (int kk = 0; kk < 16; kk++) {
            float bv = Bs[kk][tx];
#pragma unroll
            for (int r = 0; r < 4; r++) acc[r] += As[kk][ty + 16 * r] * bv;
        }
        __syncthreads();
    }
    int col = col0 + tx;
    if (col < OUTD) {
#pragma unroll
        for (int r = 0; r < 4; r++)
            g_ro_part[(ks * B_ + m0 + ty + 16 * r) * OUTD + col] = acc[r];
    }
}

// ---------------- stack update + (decoder) log_softmax/argmax/output -------------
// one block per batch element, 256 threads.
__global__ __launch_bounds__(256) void stack_kernel(
    const float* __restrict__ b_ro, int t, int colStart, int isDec, int td,
    float* __restrict__ y)
{
    __shared__ float sh_out[OUTD];
    __shared__ float sc[256];
    __shared__ float scoeff[256];
    __shared__ int   si[256];

    int b = blockIdx.x, tid = threadIdx.x;

    // reduce split-K readout partials + bias
    for (int col = colStart + tid; col < OUTD; col += 256) {
        float v = b_ro[col];
#pragma unroll
        for (int ks = 0; ks < 4; ks++) v += g_ro_part[(ks * B_ + b) * OUTD + col];
        sh_out[col] = v;
    }
    __syncthreads();

    float dtv = sigf(sh_out[192]);
    float utv = sigf(sh_out[193]);

    // V[t] = vt
    if (tid < DS) g_V[((size_t)t * B_ + b) * DS + tid] = sh_out[DIN + tid];

    // load s (entries >= t are zero by construction)
    float sv = (tid < t) ? g_s[tid * B_ + b] : 0.f;

    // scan 1 (inclusive, Hillis-Steele over 256)
    sc[tid] = sv; __syncthreads();
    for (int off = 1; off < 256; off <<= 1) {
        float add = (tid >= off) ? sc[tid - off] : 0.f;
        __syncthreads();
        sc[tid] += add;
        __syncthreads();
    }
    float cum1 = sc[tid];
    float total1 = (t > 0) ? sc[t - 1] : 0.f;
    __syncthreads();

    // pop (only when t > 0), then push s[t] = dt
    if (t > 0 && tid < t) {
        float part = total1 - cum1;
        sv = fmaxf(0.f, sv - fmaxf(0.f, utv - part));
    }
    if (tid == t) sv = dtv;

    // scan 2
    sc[tid] = sv; __syncthreads();
    for (int off = 1; off < 256; off <<= 1) {
        float add = (tid >= off) ? sc[tid - off] : 0.f;
        __syncthreads();
        sc[tid] += add;
        __syncthreads();
    }
    float cum2 = sc[tid];
    float total2 = sc[t];
    __syncthreads();

    float coeff = 0.f;
    if (tid <= t) {
        float part = (tid < t) ? (total2 - cum2) : total2;
        float a = fmaxf(0.f, 1.f - part);
        coeff = fminf(sv, a);
        g_s[tid * B_ + b] = sv;
    }
    scoeff[tid] = coeff;
    __syncthreads();

    // rt[b,d] = sum_i coeff[i] * V[i,b,d]
    int d = tid & 63, grp = tid >> 6;
    float racc = 0.f;
    for (int i = grp; i <= t; i += 4)
        racc += scoeff[i] * g_V[((size_t)i * B_ + b) * DS + d];
    sc[tid] = racc; __syncthreads();
    if (tid < DS) g_rt[b * DS + tid] = sc[tid] + sc[64 + tid] + sc[128 + tid] + sc[192 + tid];

    if (isDec) {
        __syncthreads();
        float xv = (tid < DIN) ? sh_out[tid] : -3.4e38f;
        // max
        sc[tid] = xv; __syncthreads();
        for (int off = 128; off > 0; off >>= 1) {
            if (tid < off) sc[tid] = fmaxf(sc[tid], sc[tid + off]);
            __syncthreads();
        }
        float mx = sc[0]; __syncthreads();
        // sum exp
        float ex = (tid < DIN) ? expf(xv - mx) : 0.f;
        sc[tid] = ex; __syncthreads();
        for (int off = 128; off > 0; off >>= 1) {
            if (tid < off) sc[tid] += sc[tid + off];
            __syncthreads();
        }
        float lz = logf(sc[0]); __syncthreads();
        // argmax = lowest index attaining max (bitwise-equal fp32 compare)
        si[tid] = (tid < DIN && xv == mx) ? tid : (1 << 30);
        __syncthreads();
        for (int off = 128; off > 0; off >>= 1) {
            if (tid < off) si[tid] = min(si[tid], si[tid + off]);
            __syncthreads();
        }
        int amax = si[0];

        float bd = g_done[b];
        if (tid < DIN) {
            float logp = xv - mx - lz;
            float bc = (tid == 0) ? 1.f : 0.f;
            y[((size_t)td * B_ + b) * DIN + tid] = (1.f - bd) * logp + bd * bc;
        }
        __syncthreads();   // all reads of bd complete before update
        if (tid == 0) {
            float dn = (amax == 2) ? 1.f : 0.f;
            g_done[b] = fmaxf(bd, dn);
        }
    }
}

// ---------------- launch ----------------
extern "C" void kernel_launch(void* const* d_in, const int* in_sizes, int n_in,
                              void* d_out, int out_size)
{
    const float* x        = (const float*)d_in[0];
    const float* w_ih_enc = (const float*)d_in[1];
    const float* w_hh_enc = (const float*)d_in[2];
    const float* b_ih_enc = (const float*)d_in[3];
    const float* b_hh_enc = (const float*)d_in[4];
    const float* w_ih_dec = (const float*)d_in[5];
    const float* w_hh_dec = (const float*)d_in[6];
    const float* b_ih_dec = (const float*)d_in[7];
    const float* b_hh_dec = (const float*)d_in[8];
    const float* w_ro     = (const float*)d_in[9];
    const float* b_ro     = (const float*)d_in[10];
    float* y = (float*)d_out;

    init_kernel<<<256, 256>>>();

    int g = 0;
    for (int t = 0; t < NENC; t++, g++) {
        lstm_step_kernel<<<dim3(4, 32), 256>>>(x, t, g & 1,
                                               w_ih_enc, w_hh_enc, b_ih_enc, b_hh_enc, 0);
        ro_kernel<<<dim3(4, 5, 4), 256>>>((g & 1) ^ 1, w_ro, 128);   // only cols 128..193 needed
        stack_kernel<<<256, 256>>>(b_ro, t, 128, 0, 0, y);
    }
    for (int td = 0; td < NDEC; td++, g++) {
        lstm_step_kernel<<<dim3(4, 32), 256>>>(x, 0, g & 1,
                                               w_ih_dec, w_hh_dec, b_ih_dec, b_hh_dec, 128); // x0 = 0
        ro_kernel<<<dim3(4, 13, 4), 256>>>((g & 1) ^ 1, w_ro, 0);
        stack_kernel<<<256, 256>>>(b_ro, 65 + td, 0, 1, td, y);
    }
}

// round 2
// speedup vs baseline: 1.0088x; 1.0088x over previous
#include <cuda_runtime.h>
#include <math.h>

#define B_   256
#define H_   1024
#define DIN  128
#define DS   64
#define KTOT 1216
#define MAXT 129
#define OUTD 194
#define NENC 65
#define NDEC 64

// ---------------- persistent state (device globals; no allocation) ----------------
__device__ float g_h[2][B_ * H_];
__device__ float g_c[B_ * H_];
__device__ float g_rt[B_ * DS];
__device__ float g_V[(size_t)MAXT * B_ * DS];
__device__ float g_s[MAXT * B_];
__device__ float g_done[B_];
__device__ float g_ro_part[4 * B_ * OUTD];

__device__ __forceinline__ float sigf(float x) { return 1.0f / (1.0f + expf(-x)); }

// ---------------- zero-init (every launch: determinism) ----------------
__global__ void init_kernel() {
    int i = blockIdx.x * blockDim.x + threadIdx.x;
    int n = blockDim.x * gridDim.x;
    for (int j = i; j < B_ * H_; j += n) { g_h[0][j] = 0.f; g_h[1][j] = 0.f; g_c[j] = 0.f; }
    for (int j = i; j < B_ * DS; j += n) g_rt[j] = 0.f;
    for (int j = i; j < MAXT * B_; j += n) g_s[j] = 0.f;
    for (int j = i; j < B_; j += n) g_done[j] = 0.f;
}

// ---------------- fused gates GEMM + LSTM pointwise ----------------
// gates(B=256, 4096) = [xt | rt | h_in](256,1216) @ W^T, W row n = gi*1024 + j
// Tile: 64 batch x 32 hidden units (=128 gate cols). grid(4,32), 256 threads.
// Each thread: 4 batches x 2 j x 4 gates = 32 accumulators.
__global__ __launch_bounds__(256) void lstm_step_kernel(
    const float* __restrict__ x, int t, int parity,
    const float* __restrict__ w_ih, const float* __restrict__ w_hh,
    const float* __restrict__ b_ih, const float* __restrict__ b_hh,
    int kStart)
{
    __shared__ float As[16][64];
    __shared__ float Bs[16][128];

    const float* h_in  = g_h[parity];
    float*       h_out = g_h[parity ^ 1];
    const float* xt = x + (size_t)t * B_ * DIN;

    int tid = threadIdx.x;
    int tx = tid & 15, ty = tid >> 4;
    int m0 = blockIdx.x * 64;
    int j0 = blockIdx.y * 32;

    float acc[4][2][4];
#pragma unroll
    for (int r = 0; r < 4; r++)
#pragma unroll
        for (int q = 0; q < 2; q++)
#pragma unroll
            for (int gi = 0; gi < 4; gi++) acc[r][q][gi] = 0.f;

    // loader indices
    int lm  = tid >> 2;           // 0..63 (batch within tile)
    int lk4 = (tid & 3) << 2;     // 0,4,8,12
    int ln  = tid >> 1;           // 0..127 (gate-col within tile)
    int lgi = ln >> 5, ljl = ln & 31;
    int lk8 = (tid & 1) << 3;     // 0,8
    const float* wrow_ih = w_ih + (size_t)(lgi * H_ + j0 + ljl) * 192;
    const float* wrow_hh = w_hh + (size_t)(lgi * H_ + j0 + ljl) * H_;

    for (int k0 = kStart; k0 < KTOT; k0 += 16) {
        // A tile (the 16-wide k slab never straddles the 128/192 boundaries)
        float4 va;
        if (k0 < 128)      va = *(const float4*)(xt   + (m0 + lm) * DIN + k0 + lk4);
        else if (k0 < 192) va = *(const float4*)(g_rt + (m0 + lm) * DS  + (k0 - 128) + lk4);
        else               va = *(const float4*)(h_in + (m0 + lm) * H_  + (k0 - 192) + lk4);
        As[lk4 + 0][lm] = va.x; As[lk4 + 1][lm] = va.y;
        As[lk4 + 2][lm] = va.z; As[lk4 + 3][lm] = va.w;

        // B tile
        const float* p = (k0 < 192) ? (wrow_ih + k0 + lk8) : (wrow_hh + (k0 - 192) + lk8);
        float4 vb0 = *(const float4*)p;
        float4 vb1 = *(const float4*)(p + 4);
        Bs[lk8 + 0][ln] = vb0.x; Bs[lk8 + 1][ln] = vb0.y;
        Bs[lk8 + 2][ln] = vb0.z; Bs[lk8 + 3][ln] = vb0.w;
        Bs[lk8 + 4][ln] = vb1.x; Bs[lk8 + 5][ln] = vb1.y;
        Bs[lk8 + 6][ln] = vb1.z; Bs[lk8 + 7][ln] = vb1.w;
        __syncthreads();

#pragma unroll
        for (int kk = 0; kk < 16; kk++) {
            float rA[4], rB[2][4];
#pragma unroll
            for (int r = 0; r < 4; r++) rA[r] = As[kk][ty + 16 * r];
#pragma unroll
            for (int q = 0; q < 2; q++)
#pragma unroll
                for (int gi = 0; gi < 4; gi++) rB[q][gi] = Bs[kk][gi * 32 + tx + 16 * q];
#pragma unroll
            for (int r = 0; r < 4; r++)
#pragma unroll
                for (int q = 0; q < 2; q++)
#pragma unroll
                    for (int gi = 0; gi < 4; gi++) acc[r][q][gi] += rA[r] * rB[q][gi];
        }
        __syncthreads();
    }

    // epilogue: LSTM pointwise
#pragma unroll
    for (int r = 0; r < 4; r++) {
        int m = m0 + ty + 16 * r;
#pragma unroll
        for (int q = 0; q < 2; q++) {
            int j = j0 + tx + 16 * q;
            float gi_v = acc[r][q][0] + b_ih[j]            + b_hh[j];
            float gf_v = acc[r][q][1] + b_ih[H_ + j]       + b_hh[H_ + j];
            float gg_v = acc[r][q][2] + b_ih[2 * H_ + j]   + b_hh[2 * H_ + j];
            float go_v = acc[r][q][3] + b_ih[3 * H_ + j]   + b_hh[3 * H_ + j];
            float cv = g_c[m * H_ + j];
            float cn = sigf(gf_v) * cv + sigf(gi_v) * tanhf(gg_v);
            float hn = sigf(go_v) * tanhf(cn);
            g_c[m * H_ + j]  = cn;
            h_out[m * H_ + j] = hn;
        }
    }
}

// ---------------- readout GEMM: out = h_new @ w_ro^T (split-K x4, partials) ----------
// grid(4, colTiles, 4), 256 threads. Tile 64 batch x 16 cols. K chunk = 256.
__global__ __launch_bounds__(256) void ro_kernel(
    int parityNew, const float* __restrict__ w_ro, int colStart)
{
    __shared__ float As[16][64];
    __shared__ float Bs[16][17];

    const float* h = g_h[parityNew];
    int tid = threadIdx.x;
    int tx = tid & 15, ty = tid >> 4;
    int m0 = blockIdx.x * 64;
    int col0 = colStart + blockIdx.y * 16;
    int ks = blockIdx.z;

    float acc[4] = {0.f, 0.f, 0.f, 0.f};
    int lm = tid >> 2, lk4 = (tid & 3) << 2;
    int myCol = col0 + ty;
    bool colOk = (myCol < OUTD);

    int kend = ks * 256 + 256;
    for (int k0 = ks * 256; k0 < kend; k0 += 16) {
        float4 va = *(const float4*)(h + (m0 + lm) * H_ + k0 + lk4);
        As[lk4 + 0][lm] = va.x; As[lk4 + 1][lm] = va.y;
        As[lk4 + 2][lm] = va.z; As[lk4 + 3][lm] = va.w;
        Bs[tx][ty] = colOk ? w_ro[(size_t)myCol * H_ + k0 + tx] : 0.f;
        __syncthreads();
#pragma unroll
        for (int kk = 0; kk < 16; kk++) {
            float bv = Bs[kk][tx];
#pragma unroll
            for (int r = 0; r < 4; r++) acc[r] += As[kk][ty + 16 * r] * bv;
        }
        __syncthreads();
    }
    int col = col0 + tx;
    if (col < OUTD) {
#pragma unroll
        for (int r = 0; r < 4; r++)
            g_ro_part[(ks * B_ + m0 + ty + 16 * r) * OUTD + col] = acc[r];
    }
}

// ---------------- stack update + (decoder) log_softmax/argmax/output -------------
// one block per batch element, 256 threads.
__global__ __launch_bounds__(256) void stack_kernel(
    const float* __restrict__ b_ro, int t, int colStart, int isDec, int td,
    float* __restrict__ y)
{
    __shared__ float sh_out[OUTD];
    __shared__ float sc[256];
    __shared__ float scoeff[256];
    __shared__ int   si[256];

    int b = blockIdx.x, tid = threadIdx.x;

    // reduce split-K readout partials + bias
    for (int col = colStart + tid; col < OUTD; col += 256) {
        float v = b_ro[col];
#pragma unroll
        for (int ks = 0; ks < 4; ks++) v += g_ro_part[(ks * B_ + b) * OUTD + col];
        sh_out[col] = v;
    }
    __syncthreads();

    float dtv = sigf(sh_out[192]);
    float utv = sigf(sh_out[193]);

    // V[t] = vt
    if (tid < DS) g_V[((size_t)t * B_ + b) * DS + tid] = sh_out[DIN + tid];

    // load s (entries >= t are zero by construction)
    float sv = (tid < t) ? g_s[tid * B_ + b] : 0.f;

    // scan 1 (inclusive, Hillis-Steele over 256)
    sc[tid] = sv; __syncthreads();
    for (int off = 1; off < 256; off <<= 1) {
        float add = (tid >= off) ? sc[tid - off] : 0.f;
        __syncthreads();
        sc[tid] += add;
        __syncthreads();
    }
    float cum1 = sc[tid];
    float total1 = (t > 0) ? sc[t - 1] : 0.f;
    __syncthreads();

    // pop (only when t > 0), then push s[t] = dt
    if (t > 0 && tid < t) {
        float part = total1 - cum1;
        sv = fmaxf(0.f, sv - fmaxf(0.f, utv - part));
    }
    if (tid == t) sv = dtv;

    // scan 2
    sc[tid] = sv; __syncthreads();
    for (int off = 1; off < 256; off <<= 1) {
        float add = (tid >= off) ? sc[tid - off] : 0.f;
        __syncthreads();
        sc[tid] += add;
        __syncthreads();
    }
    float cum2 = sc[tid];
    float total2 = sc[t];
    __syncthreads();

    float coeff = 0.f;
    if (tid <= t) {
        float part = (tid < t) ? (total2 - cum2) : total2;
        float a = fmaxf(0.f, 1.f - part);
        coeff = fminf(sv, a);
        g_s[tid * B_ + b] = sv;
    }
    scoeff[tid] = coeff;
    __syncthreads();

    // rt[b,d] = sum_i coeff[i] * V[i,b,d]
    int d = tid & 63, grp = tid >> 6;
    float racc = 0.f;
    for (int i = grp; i <= t; i += 4)
        racc += scoeff[i] * g_V[((size_t)i * B_ + b) * DS + d];
    sc[tid] = racc; __syncthreads();
    if (tid < DS) g_rt[b * DS + tid] = sc[tid] + sc[64 + tid] + sc[128 + tid] + sc[192 + tid];

    if (isDec) {
        __syncthreads();
        float xv = (tid < DIN) ? sh_out[tid] : -3.4e38f;
        // max
        sc[tid] = xv; __syncthreads();
        for (int off = 128; off > 0; off >>= 1) {
            if (tid < off) sc[tid] = fmaxf(sc[tid], sc[tid + off]);
            __syncthreads();
        }
        float mx = sc[0]; __syncthreads();
        // sum exp
        float ex = (tid < DIN) ? expf(xv - mx) : 0.f;
        sc[tid] = ex; __syncthreads();
        for (int off = 128; off > 0; off >>= 1) {
            if (tid < off) sc[tid] += sc[tid + off];
            __syncthreads();
        }
        float lz = logf(sc[0]); __syncthreads();
        // argmax = lowest index attaining max (bitwise-equal fp32 compare)
        si[tid] = (tid < DIN && xv == mx) ? tid : (1 << 30);
        __syncthreads();
        for (int off = 128; off > 0; off >>= 1) {
            if (tid < off) si[tid] = min(si[tid], si[tid + off]);
            __syncthreads();
        }
        int amax = si[0];

        float bd = g_done[b];
        if (tid < DIN) {
            float logp = xv - mx - lz;
            float bc = (tid == 0) ? 1.f : 0.f;
            y[((size_t)td * B_ + b) * DIN + tid] = (1.f - bd) * logp + bd * bc;
        }
        __syncthreads();   // all reads of bd complete before update
        if (tid == 0) {
            float dn = (amax == 2) ? 1.f : 0.f;
            g_done[b] = fmaxf(bd, dn);
        }
    }
}

// ---------------- launch ----------------
extern "C" void kernel_launch(void* const* d_in, const int* in_sizes, int n_in,
                              void* d_out, int out_size)
{
    const float* x        = (const float*)d_in[0];
    const float* w_ih_enc = (const float*)d_in[1];
    const float* w_hh_enc = (const float*)d_in[2];
    const float* b_ih_enc = (const float*)d_in[3];
    const float* b_hh_enc = (const float*)d_in[4];
    const float* w_ih_dec = (const float*)d_in[5];
    const float* w_hh_dec = (const float*)d_in[6];
    const float* b_ih_dec = (const float*)d_in[7];
    const float* b_hh_dec = (const float*)d_in[8];
    const float* w_ro     = (const float*)d_in[9];
    const float* b_ro     = (const float*)d_in[10];
    float* y = (float*)d_out;

    init_kernel<<<256, 256>>>();

    int g = 0;
    for (int t = 0; t < NENC; t++, g++) {
        lstm_step_kernel<<<dim3(4, 32), 256>>>(x, t, g & 1,
                                               w_ih_enc, w_hh_enc, b_ih_enc, b_hh_enc, 0);
        ro_kernel<<<dim3(4, 5, 4), 256>>>((g & 1) ^ 1, w_ro, 128);   // only cols 128..193 needed
        stack_kernel<<<256, 256>>>(b_ro, t, 128, 0, 0, y);
    }
    for (int td = 0; td < NDEC; td++, g++) {
        lstm_step_kernel<<<dim3(4, 32), 256>>>(x, 0, g & 1,
                                               w_ih_dec, w_hh_dec, b_ih_dec, b_hh_dec, 128); // x0 = 0
        ro_kernel<<<dim3(4, 13, 4), 256>>>((g & 1) ^ 1, w_ro, 0);
        stack_kernel<<<256, 256>>>(b_ro, 65 + td, 0, 1, td, y);
    }
}